// round 2
// baseline (speedup 1.0000x reference)
#include <cuda_runtime.h>
#include <math.h>

#define NN   50000
#define DD   128
#define SS   25
#define TM   64            // rows per CTA tile
#define NBLK ((NN + TM - 1) / TM)   // 782

// ---------------- scratch (device globals; no allocation allowed) ----------
__device__ float g_h1[NN * DD];
__device__ float g_x [NN * DD];
__device__ float g_xn[NN * DD];
__device__ float g_h2[NN * DD];
__device__ float g_psum  [NBLK * DD];
__device__ float g_psumsq[NBLK * DD];
__device__ float g_scale[DD];
__device__ float g_shift[DD];

// ---------------------------------------------------------------------------
// Kernel: O[rows,128] = relu(A[rows,128] @ W[128,128] + b)
// 256 threads, TM=64 row tile. W resident in smem. 8x4 micro-tile per thread.
// ---------------------------------------------------------------------------
__global__ __launch_bounds__(256) void gemm128_relu(
    const float* __restrict__ A, const float* __restrict__ W,
    const float* __restrict__ bias, float* __restrict__ O, int nrows)
{
    extern __shared__ float sm[];
    float* Ws = sm;               // 128*128 floats
    float* As = sm + 128 * 128;   // 64*128  floats

    const int tid = threadIdx.x;
    const int tileBase = blockIdx.x * TM;

    // load weight (16384 floats = 4096 float4)
    const float4* Wg4 = (const float4*)W;
    float4* Ws4 = (float4*)Ws;
    #pragma unroll
    for (int i = 0; i < 16; i++) Ws4[tid + i * 256] = Wg4[tid + i * 256];

    // load A tile (2048 float4)
    #pragma unroll
    for (int i = 0; i < 8; i++) {
        int idx = tid + i * 256;
        int r = idx >> 5, c = idx & 31;
        int row = tileBase + r;
        float4 v = make_float4(0.f, 0.f, 0.f, 0.f);
        if (row < nrows) v = ((const float4*)(A + (size_t)row * DD))[c];
        ((float4*)As)[idx] = v;
    }
    __syncthreads();

    const int ty = tid >> 5, tx = tid & 31;
    float acc[8][4];
    #pragma unroll
    for (int r = 0; r < 8; r++)
        acc[r][0] = acc[r][1] = acc[r][2] = acc[r][3] = 0.f;

    const float* Abase = As + (ty * 8) * DD;
    #pragma unroll 2
    for (int k = 0; k < DD; k += 4) {
        float4 a[8];
        #pragma unroll
        for (int r = 0; r < 8; r++)
            a[r] = *(const float4*)(Abase + r * DD + k);
        #pragma unroll
        for (int kk = 0; kk < 4; kk++) {
            float4 w = ((const float4*)(Ws + (k + kk) * DD))[tx];
            #pragma unroll
            for (int r = 0; r < 8; r++) {
                float av = (kk == 0) ? a[r].x : (kk == 1) ? a[r].y
                         : (kk == 2) ? a[r].z : a[r].w;
                acc[r][0] = fmaf(av, w.x, acc[r][0]);
                acc[r][1] = fmaf(av, w.y, acc[r][1]);
                acc[r][2] = fmaf(av, w.z, acc[r][2]);
                acc[r][3] = fmaf(av, w.w, acc[r][3]);
            }
        }
    }

    float4 b4 = ((const float4*)bias)[tx];
    #pragma unroll
    for (int r = 0; r < 8; r++) {
        int row = tileBase + ty * 8 + r;
        if (row < nrows) {
            float4 o;
            o.x = fmaxf(acc[r][0] + b4.x, 0.f);
            o.y = fmaxf(acc[r][1] + b4.y, 0.f);
            o.z = fmaxf(acc[r][2] + b4.z, 0.f);
            o.w = fmaxf(acc[r][3] + b4.w, 0.f);
            ((float4*)(O + (size_t)row * DD))[tx] = o;
        }
    }
}

// ---------------------------------------------------------------------------
// Fused: agg[n,:] = max_{s<25} H[idx[n,s],:],  then
//        O = act( concat(A0, agg) @ W[256,128] + b )
// Optionally accumulates per-column sum / sumsq of activated output
// (deterministic per-CTA partials, reduced later).
// ---------------------------------------------------------------------------
template<bool RELU, bool BNSTATS>
__global__ __launch_bounds__(256) void gather_gemm256(
    const float* __restrict__ A0, const float* __restrict__ H,
    const int* __restrict__ nidx, const float* __restrict__ W,
    const float* __restrict__ bias, float* __restrict__ O, int nrows)
{
    extern __shared__ float sm[];
    float* Ws = sm;               // 256*128 floats (128 KB)
    float* As = sm + 256 * 128;   // 64*256  floats (64 KB)

    const int tid = threadIdx.x;
    const int tileBase = blockIdx.x * TM;
    const int ty = tid >> 5, tx = tid & 31;

    // load weight (32768 floats = 8192 float4)
    const float4* Wg4 = (const float4*)W;
    float4* Ws4 = (float4*)Ws;
    #pragma unroll
    for (int i = 0; i < 32; i++) Ws4[tid + i * 256] = Wg4[tid + i * 256];

    // load self features into As[r][0..127]
    #pragma unroll
    for (int i = 0; i < 8; i++) {
        int idx = tid + i * 256;
        int r = idx >> 5, c = idx & 31;
        int row = tileBase + r;
        float4 v = make_float4(0.f, 0.f, 0.f, 0.f);
        if (row < nrows) v = ((const float4*)(A0 + (size_t)row * DD))[c];
        ((float4*)(As + r * 256))[c] = v;
    }

    // gather-max into As[r][128..255]; warp ty owns rows ty*8..ty*8+7.
    // (H = relu(...) >= 0, so init 0 is exact.)
    #pragma unroll
    for (int r = 0; r < 8; r++) {
        int row = tileBase + ty * 8 + r;
        float4 m = make_float4(0.f, 0.f, 0.f, 0.f);
        if (row < nrows) {
            const int* ip = nidx + (size_t)row * SS;
            int myi = (tx < SS) ? ip[tx] : 0;
            #pragma unroll
            for (int s = 0; s < SS; s++) {
                int j = __shfl_sync(0xffffffffu, myi, s);
                float4 v = ((const float4*)(H + (size_t)j * DD))[tx];
                m.x = fmaxf(m.x, v.x);
                m.y = fmaxf(m.y, v.y);
                m.z = fmaxf(m.z, v.z);
                m.w = fmaxf(m.w, v.w);
            }
        }
        ((float4*)(As + (ty * 8 + r) * 256 + 128))[tx] = m;
    }
    __syncthreads();

    float acc[8][4];
    #pragma unroll
    for (int r = 0; r < 8; r++)
        acc[r][0] = acc[r][1] = acc[r][2] = acc[r][3] = 0.f;

    const float* Abase = As + (ty * 8) * 256;
    #pragma unroll 2
    for (int k = 0; k < 256; k += 4) {
        float4 a[8];
        #pragma unroll
        for (int r = 0; r < 8; r++)
            a[r] = *(const float4*)(Abase + r * 256 + k);
        #pragma unroll
        for (int kk = 0; kk < 4; kk++) {
            float4 w = ((const float4*)(Ws + (k + kk) * DD))[tx];
            #pragma unroll
            for (int r = 0; r < 8; r++) {
                float av = (kk == 0) ? a[r].x : (kk == 1) ? a[r].y
                         : (kk == 2) ? a[r].z : a[r].w;
                acc[r][0] = fmaf(av, w.x, acc[r][0]);
                acc[r][1] = fmaf(av, w.y, acc[r][1]);
                acc[r][2] = fmaf(av, w.z, acc[r][2]);
                acc[r][3] = fmaf(av, w.w, acc[r][3]);
            }
        }
    }

    float4 b4 = ((const float4*)bias)[tx];
    float cs[4] = {0.f, 0.f, 0.f, 0.f};
    float cq[4] = {0.f, 0.f, 0.f, 0.f};
    #pragma unroll
    for (int r = 0; r < 8; r++) {
        int row = tileBase + ty * 8 + r;
        if (row < nrows) {
            float4 o;
            o.x = acc[r][0] + b4.x;
            o.y = acc[r][1] + b4.y;
            o.z = acc[r][2] + b4.z;
            o.w = acc[r][3] + b4.w;
            if (RELU) {
                o.x = fmaxf(o.x, 0.f); o.y = fmaxf(o.y, 0.f);
                o.z = fmaxf(o.z, 0.f); o.w = fmaxf(o.w, 0.f);
            }
            ((float4*)(O + (size_t)row * DD))[tx] = o;
            if (BNSTATS) {
                cs[0] += o.x; cs[1] += o.y; cs[2] += o.z; cs[3] += o.w;
                cq[0] += o.x * o.x; cq[1] += o.y * o.y;
                cq[2] += o.z * o.z; cq[3] += o.w * o.w;
            }
        }
    }

    if (BNSTATS) {
        __syncthreads();               // done reading As; reuse for reduction
        float* red = As;               // [8][128] sums + [8][128] sumsq
        #pragma unroll
        for (int c = 0; c < 4; c++) {
            red[ty * 128 + tx * 4 + c]        = cs[c];
            red[1024 + ty * 128 + tx * 4 + c] = cq[c];
        }
        __syncthreads();
        if (tid < 128) {
            float s = 0.f, q = 0.f;
            #pragma unroll
            for (int w = 0; w < 8; w++) {
                s += red[w * 128 + tid];
                q += red[1024 + w * 128 + tid];
            }
            g_psum  [blockIdx.x * DD + tid] = s;
            g_psumsq[blockIdx.x * DD + tid] = q;
        }
    }
}

// ---------------------------------------------------------------------------
// Reduce per-CTA BN partials; produce fused scale/shift.
// ---------------------------------------------------------------------------
__global__ void bn_finalize(const float* __restrict__ gamma,
                            const float* __restrict__ beta)
{
    int t = threadIdx.x;   // 128 threads
    float s = 0.f, q = 0.f;
    for (int i = 0; i < NBLK; i++) {
        s += g_psum  [i * DD + t];
        q += g_psumsq[i * DD + t];
    }
    float mean = s * (1.0f / NN);
    float var  = q * (1.0f / NN) - mean * mean;
    float sc   = gamma[t] * rsqrtf(var + 1e-5f);
    g_scale[t] = sc;
    g_shift[t] = beta[t] - mean * sc;
}

// ---------------------------------------------------------------------------
// xn[n,:] = bn(x[n,:]) / (||bn(x[n,:])||_2 + 1e-6).  One warp per row.
// ---------------------------------------------------------------------------
__global__ __launch_bounds__(256) void bn_rownorm(
    const float* __restrict__ X, float* __restrict__ XN, int nrows)
{
    const int ty = threadIdx.x >> 5, tx = threadIdx.x & 31;
    const int row = blockIdx.x * 8 + ty;
    if (row >= nrows) return;

    float4 v  = ((const float4*)(X + (size_t)row * DD))[tx];
    float4 sc = ((const float4*)g_scale)[tx];
    float4 sh = ((const float4*)g_shift)[tx];
    v.x = fmaf(v.x, sc.x, sh.x);
    v.y = fmaf(v.y, sc.y, sh.y);
    v.z = fmaf(v.z, sc.z, sh.z);
    v.w = fmaf(v.w, sc.w, sh.w);

    float ss = v.x * v.x + v.y * v.y + v.z * v.z + v.w * v.w;
    #pragma unroll
    for (int off = 16; off > 0; off >>= 1)
        ss += __shfl_xor_sync(0xffffffffu, ss, off);

    float inv = 1.0f / (sqrtf(ss) + 1e-6f);
    v.x *= inv; v.y *= inv; v.z *= inv; v.w *= inv;
    ((float4*)(XN + (size_t)row * DD))[tx] = v;
}

// ---------------------------------------------------------------------------
extern "C" void kernel_launch(void* const* d_in, const int* in_sizes, int n_in,
                              void* d_out, int out_size)
{
    const float* features = (const float*)d_in[0];
    const int*   idx1     = (const int*)  d_in[1];
    const int*   idx2     = (const int*)  d_in[2];
    const float* agg1_W   = (const float*)d_in[3];
    const float* agg1_b   = (const float*)d_in[4];
    const float* fc1_W    = (const float*)d_in[5];
    const float* fc1_b    = (const float*)d_in[6];
    const float* agg2_W   = (const float*)d_in[7];
    const float* agg2_b   = (const float*)d_in[8];
    const float* fc2_W    = (const float*)d_in[9];
    const float* fc2_b    = (const float*)d_in[10];
    const float* gamma    = (const float*)d_in[11];
    const float* beta     = (const float*)d_in[12];
    float* out = (float*)d_out;

    const int smem128 = (128 * 128 + TM * 128) * (int)sizeof(float);   //  98304
    const int smem256 = (256 * 128 + TM * 256) * (int)sizeof(float);   // 196608
    cudaFuncSetAttribute(gemm128_relu,
        cudaFuncAttributeMaxDynamicSharedMemorySize, smem128);
    cudaFuncSetAttribute(gather_gemm256<true, true>,
        cudaFuncAttributeMaxDynamicSharedMemorySize, smem256);
    cudaFuncSetAttribute(gather_gemm256<false, false>,
        cudaFuncAttributeMaxDynamicSharedMemorySize, smem256);

    float *h1, *x, *xn, *h2;
    cudaGetSymbolAddress((void**)&h1, g_h1);
    cudaGetSymbolAddress((void**)&x,  g_x);
    cudaGetSymbolAddress((void**)&xn, g_xn);
    cudaGetSymbolAddress((void**)&h2, g_h2);

    // ---- layer 1 ----
    gemm128_relu<<<NBLK, 256, smem128>>>(features, agg1_W, agg1_b, h1, NN);
    gather_gemm256<true, true><<<NBLK, 256, smem256>>>(
        features, h1, idx1, fc1_W, fc1_b, x, NN);
    bn_finalize<<<1, 128>>>(gamma, beta);
    bn_rownorm<<<(NN + 7) / 8, 256>>>(x, xn, NN);

    // ---- layer 2 ----
    gemm128_relu<<<NBLK, 256, smem128>>>(xn, agg2_W, agg2_b, h2, NN);
    gather_gemm256<false, false><<<NBLK, 256, smem256>>>(
        xn, h2, idx2, fc2_W, fc2_b, out, NN);
}

// round 3
// speedup vs baseline: 1.1080x; 1.1080x over previous
#include <cuda_runtime.h>
#include <math.h>

#define NN   50000
#define DD   128
#define SS   25
#define TM   64            // rows per CTA tile
#define NBLK ((NN + TM - 1) / TM)   // 782

typedef unsigned long long u64;

// ---------------- scratch (device globals; no allocation allowed) ----------
__device__ float g_h1[NN * DD];
__device__ float g_x [NN * DD];
__device__ float g_xn[NN * DD];
__device__ float g_h2[NN * DD];
__device__ float g_psum  [NBLK * DD];
__device__ float g_psumsq[NBLK * DD];
__device__ float g_scale[DD];
__device__ float g_shift[DD];

// ---------------- packed f32x2 helpers -------------------------------------
__device__ __forceinline__ u64 pk2(float lo, float hi) {
    u64 r;
    asm("mov.b64 %0, {%1, %2};" : "=l"(r) : "f"(lo), "f"(hi));
    return r;
}
__device__ __forceinline__ void fma2(u64& d, u64 a, u64 b) {
    asm("fma.rn.f32x2 %0, %1, %2, %0;" : "+l"(d) : "l"(a), "l"(b));
}
__device__ __forceinline__ float2 upk2(u64 v) {
    float2 r;
    asm("mov.b64 {%0, %1}, %2;" : "=f"(r.x), "=f"(r.y) : "l"(v));
    return r;
}

// ---------------------------------------------------------------------------
// O[rows,128] = relu(A[rows,128] @ W[128,128] + b)
// 256 threads, TM=64 row tile, W resident in smem.
// Each thread: 8 rows x 4 cols, packed f32x2 over column pairs.
// ---------------------------------------------------------------------------
__global__ __launch_bounds__(256) void gemm128_relu(
    const float* __restrict__ A, const float* __restrict__ W,
    const float* __restrict__ bias, float* __restrict__ O, int nrows)
{
    extern __shared__ float sm[];
    float* Ws = sm;               // 128*128 floats
    float* As = sm + 128 * 128;   // 64*128  floats

    const int tid = threadIdx.x;
    const int tileBase = blockIdx.x * TM;

    const float4* Wg4 = (const float4*)W;
    float4* Ws4 = (float4*)Ws;
    #pragma unroll
    for (int i = 0; i < 16; i++) Ws4[tid + i * 256] = Wg4[tid + i * 256];

    #pragma unroll
    for (int i = 0; i < 8; i++) {
        int idx = tid + i * 256;
        int r = idx >> 5, c = idx & 31;
        int row = tileBase + r;
        float4 v = make_float4(0.f, 0.f, 0.f, 0.f);
        if (row < nrows) v = ((const float4*)(A + (size_t)row * DD))[c];
        ((float4*)As)[idx] = v;
    }
    __syncthreads();

    const int ty = tid >> 5, tx = tid & 31;
    u64 acc[8][2];
    #pragma unroll
    for (int r = 0; r < 8; r++) { acc[r][0] = 0ull; acc[r][1] = 0ull; }

    const float* Abase = As + (ty * 8) * DD;
    #pragma unroll 2
    for (int k = 0; k < DD; k += 4) {
        float4 a[8];
        #pragma unroll
        for (int r = 0; r < 8; r++)
            a[r] = *(const float4*)(Abase + r * DD + k);
        #pragma unroll
        for (int kk = 0; kk < 4; kk++) {
            ulonglong2 w = ((const ulonglong2*)(Ws + (k + kk) * DD))[tx];
            #pragma unroll
            for (int r = 0; r < 8; r++) {
                float av = (kk == 0) ? a[r].x : (kk == 1) ? a[r].y
                         : (kk == 2) ? a[r].z : a[r].w;
                u64 a2 = pk2(av, av);
                fma2(acc[r][0], a2, w.x);
                fma2(acc[r][1], a2, w.y);
            }
        }
    }

    float4 b4 = ((const float4*)bias)[tx];
    #pragma unroll
    for (int r = 0; r < 8; r++) {
        int row = tileBase + ty * 8 + r;
        if (row < nrows) {
            float2 o0 = upk2(acc[r][0]);
            float2 o1 = upk2(acc[r][1]);
            float4 o;
            o.x = fmaxf(o0.x + b4.x, 0.f);
            o.y = fmaxf(o0.y + b4.y, 0.f);
            o.z = fmaxf(o1.x + b4.z, 0.f);
            o.w = fmaxf(o1.y + b4.w, 0.f);
            ((float4*)(O + (size_t)row * DD))[tx] = o;
        }
    }
}

// ---------------------------------------------------------------------------
// Fused: agg[n,:] = max_{s<25} H[idx[n,s],:], then
//        O = act( concat(A0, agg) @ W[256,128] + b )
// Optional deterministic per-CTA BN partial sums.
// ---------------------------------------------------------------------------
template<bool RELU, bool BNSTATS>
__global__ __launch_bounds__(256) void gather_gemm256(
    const float* __restrict__ A0, const float* __restrict__ H,
    const int* __restrict__ nidx, const float* __restrict__ W,
    const float* __restrict__ bias, float* __restrict__ O, int nrows)
{
    extern __shared__ float sm[];
    float* Ws = sm;               // 256*128 floats (128 KB)
    float* As = sm + 256 * 128;   // 64*256  floats (64 KB)

    const int tid = threadIdx.x;
    const int tileBase = blockIdx.x * TM;
    const int ty = tid >> 5, tx = tid & 31;

    const float4* Wg4 = (const float4*)W;
    float4* Ws4 = (float4*)Ws;
    #pragma unroll
    for (int i = 0; i < 32; i++) Ws4[tid + i * 256] = Wg4[tid + i * 256];

    // self features into As[r][0..127]
    #pragma unroll
    for (int i = 0; i < 8; i++) {
        int idx = tid + i * 256;
        int r = idx >> 5, c = idx & 31;
        int row = tileBase + r;
        float4 v = make_float4(0.f, 0.f, 0.f, 0.f);
        if (row < nrows) v = ((const float4*)(A0 + (size_t)row * DD))[c];
        ((float4*)(As + r * 256))[c] = v;
    }

    // gather-max into As[r][128..255]  (H >= 0, so init 0 is exact)
    #pragma unroll
    for (int r = 0; r < 8; r++) {
        int row = tileBase + ty * 8 + r;
        float4 m = make_float4(0.f, 0.f, 0.f, 0.f);
        if (row < nrows) {
            const int* ip = nidx + (size_t)row * SS;
            int myi = (tx < SS) ? ip[tx] : 0;
            #pragma unroll
            for (int s = 0; s < SS; s++) {
                int j = __shfl_sync(0xffffffffu, myi, s);
                float4 v = ((const float4*)(H + (size_t)j * DD))[tx];
                m.x = fmaxf(m.x, v.x);
                m.y = fmaxf(m.y, v.y);
                m.z = fmaxf(m.z, v.z);
                m.w = fmaxf(m.w, v.w);
            }
        }
        ((float4*)(As + (ty * 8 + r) * 256 + 128))[tx] = m;
    }
    __syncthreads();

    u64 acc[8][2];
    #pragma unroll
    for (int r = 0; r < 8; r++) { acc[r][0] = 0ull; acc[r][1] = 0ull; }

    const float* Abase = As + (ty * 8) * 256;
    #pragma unroll 2
    for (int k = 0; k < 256; k += 4) {
        float4 a[8];
        #pragma unroll
        for (int r = 0; r < 8; r++)
            a[r] = *(const float4*)(Abase + r * 256 + k);
        #pragma unroll
        for (int kk = 0; kk < 4; kk++) {
            ulonglong2 w = ((const ulonglong2*)(Ws + (k + kk) * DD))[tx];
            #pragma unroll
            for (int r = 0; r < 8; r++) {
                float av = (kk == 0) ? a[r].x : (kk == 1) ? a[r].y
                         : (kk == 2) ? a[r].z : a[r].w;
                u64 a2 = pk2(av, av);
                fma2(acc[r][0], a2, w.x);
                fma2(acc[r][1], a2, w.y);
            }
        }
    }

    float4 b4 = ((const float4*)bias)[tx];
    float cs[4] = {0.f, 0.f, 0.f, 0.f};
    float cq[4] = {0.f, 0.f, 0.f, 0.f};
    #pragma unroll
    for (int r = 0; r < 8; r++) {
        int row = tileBase + ty * 8 + r;
        if (row < nrows) {
            float2 o0 = upk2(acc[r][0]);
            float2 o1 = upk2(acc[r][1]);
            float4 o;
            o.x = o0.x + b4.x;
            o.y = o0.y + b4.y;
            o.z = o1.x + b4.z;
            o.w = o1.y + b4.w;
            if (RELU) {
                o.x = fmaxf(o.x, 0.f); o.y = fmaxf(o.y, 0.f);
                o.z = fmaxf(o.z, 0.f); o.w = fmaxf(o.w, 0.f);
            }
            ((float4*)(O + (size_t)row * DD))[tx] = o;
            if (BNSTATS) {
                cs[0] += o.x; cs[1] += o.y; cs[2] += o.z; cs[3] += o.w;
                cq[0] += o.x * o.x; cq[1] += o.y * o.y;
                cq[2] += o.z * o.z; cq[3] += o.w * o.w;
            }
        }
    }

    if (BNSTATS) {
        __syncthreads();               // done reading As; reuse for reduction
        float* red = As;
        #pragma unroll
        for (int c = 0; c < 4; c++) {
            red[ty * 128 + tx * 4 + c]        = cs[c];
            red[1024 + ty * 128 + tx * 4 + c] = cq[c];
        }
        __syncthreads();
        if (tid < 128) {
            float s = 0.f, q = 0.f;
            #pragma unroll
            for (int w = 0; w < 8; w++) {
                s += red[w * 128 + tid];
                q += red[1024 + w * 128 + tid];
            }
            g_psum  [blockIdx.x * DD + tid] = s;
            g_psumsq[blockIdx.x * DD + tid] = q;
        }
    }
}

// ---------------------------------------------------------------------------
// Reduce per-CTA BN partials; produce fused scale/shift.
// 1024 threads: 8 partial-summers per column, smem tree.
// ---------------------------------------------------------------------------
__global__ __launch_bounds__(1024) void bn_finalize(
    const float* __restrict__ gamma, const float* __restrict__ beta)
{
    __shared__ float rs[1024], rq[1024];
    const int t = threadIdx.x;
    const int col = t & 127, part = t >> 7;   // 8 parts per column

    float s = 0.f, q = 0.f;
    for (int i = part; i < NBLK; i += 8) {
        s += g_psum  [i * DD + col];
        q += g_psumsq[i * DD + col];
    }
    rs[part * 128 + col] = s;
    rq[part * 128 + col] = q;
    __syncthreads();

    if (t < 128) {
        float ss = 0.f, qq = 0.f;
        #pragma unroll
        for (int p = 0; p < 8; p++) {
            ss += rs[p * 128 + t];
            qq += rq[p * 128 + t];
        }
        float mean = ss * (1.0f / NN);
        float var  = qq * (1.0f / NN) - mean * mean;
        float sc   = gamma[t] * rsqrtf(var + 1e-5f);
        g_scale[t] = sc;
        g_shift[t] = beta[t] - mean * sc;
    }
}

// ---------------------------------------------------------------------------
// xn[n,:] = bn(x[n,:]) / (||bn(x[n,:])||_2 + 1e-6).  One warp per row.
// ---------------------------------------------------------------------------
__global__ __launch_bounds__(256) void bn_rownorm(
    const float* __restrict__ X, float* __restrict__ XN, int nrows)
{
    const int ty = threadIdx.x >> 5, tx = threadIdx.x & 31;
    const int row = blockIdx.x * 8 + ty;
    if (row >= nrows) return;

    float4 v  = ((const float4*)(X + (size_t)row * DD))[tx];
    float4 sc = ((const float4*)g_scale)[tx];
    float4 sh = ((const float4*)g_shift)[tx];
    v.x = fmaf(v.x, sc.x, sh.x);
    v.y = fmaf(v.y, sc.y, sh.y);
    v.z = fmaf(v.z, sc.z, sh.z);
    v.w = fmaf(v.w, sc.w, sh.w);

    float ss = v.x * v.x + v.y * v.y + v.z * v.z + v.w * v.w;
    #pragma unroll
    for (int off = 16; off > 0; off >>= 1)
        ss += __shfl_xor_sync(0xffffffffu, ss, off);

    float inv = 1.0f / (sqrtf(ss) + 1e-6f);
    v.x *= inv; v.y *= inv; v.z *= inv; v.w *= inv;
    ((float4*)(XN + (size_t)row * DD))[tx] = v;
}

// ---------------------------------------------------------------------------
extern "C" void kernel_launch(void* const* d_in, const int* in_sizes, int n_in,
                              void* d_out, int out_size)
{
    const float* features = (const float*)d_in[0];
    const int*   idx1     = (const int*)  d_in[1];
    const int*   idx2     = (const int*)  d_in[2];
    const float* agg1_W   = (const float*)d_in[3];
    const float* agg1_b   = (const float*)d_in[4];
    const float* fc1_W    = (const float*)d_in[5];
    const float* fc1_b    = (const float*)d_in[6];
    const float* agg2_W   = (const float*)d_in[7];
    const float* agg2_b   = (const float*)d_in[8];
    const float* fc2_W    = (const float*)d_in[9];
    const float* fc2_b    = (const float*)d_in[10];
    const float* gamma    = (const float*)d_in[11];
    const float* beta     = (const float*)d_in[12];
    float* out = (float*)d_out;

    const int smem128 = (128 * 128 + TM * 128) * (int)sizeof(float);   //  98304
    const int smem256 = (256 * 128 + TM * 256) * (int)sizeof(float);   // 196608
    cudaFuncSetAttribute(gemm128_relu,
        cudaFuncAttributeMaxDynamicSharedMemorySize, smem128);
    cudaFuncSetAttribute(gather_gemm256<true, true>,
        cudaFuncAttributeMaxDynamicSharedMemorySize, smem256);
    cudaFuncSetAttribute(gather_gemm256<false, false>,
        cudaFuncAttributeMaxDynamicSharedMemorySize, smem256);

    float *h1, *x, *xn, *h2;
    cudaGetSymbolAddress((void**)&h1, g_h1);
    cudaGetSymbolAddress((void**)&x,  g_x);
    cudaGetSymbolAddress((void**)&xn, g_xn);
    cudaGetSymbolAddress((void**)&h2, g_h2);

    // ---- layer 1 ----
    gemm128_relu<<<NBLK, 256, smem128>>>(features, agg1_W, agg1_b, h1, NN);
    gather_gemm256<true, true><<<NBLK, 256, smem256>>>(
        features, h1, idx1, fc1_W, fc1_b, x, NN);
    bn_finalize<<<1, 1024>>>(gamma, beta);
    bn_rownorm<<<(NN + 7) / 8, 256>>>(x, xn, NN);

    // ---- layer 2 ----
    gemm128_relu<<<NBLK, 256, smem128>>>(xn, agg2_W, agg2_b, h2, NN);
    gather_gemm256<false, false><<<NBLK, 256, smem256>>>(
        xn, h2, idx2, fc2_W, fc2_b, out, NN);
}